// round 14
// baseline (speedup 1.0000x reference)
#include <cuda_runtime.h>
#include <cuda_bf16.h>
#include <math.h>
#include <stdint.h>

#define NS_ITERS 12
#define LAN_M 32
#define EPSc 1e-4f
#define IDESC_MAIN 0x8280490u   // f32 accum, bf16 a/b, M=128, N=160
#define W_IMG_HALF 61440
#define W_IMG_BYTES 122880
#define XS_F4 (128 * 33)
#define US_F4 (128 * 17)
#define GRID 152
#define SET_CTAS 65
#define NSC 64
#define CONV_CTAS (GRID - SET_CTAS)
#define MAX_TILES 2048

#if !defined(__CUDA_ARCH__) || defined(__CUDA_ARCH_FEAT_SM103_ALL) || defined(__CUDA_ARCH_FEAT_SM100_ALL)
#define TC_OK 1
#else
#define TC_OK 0
#endif

// ---------------- PTX helpers ----------------
__device__ __forceinline__ uint32_t smem_u32(const void* p) {
    uint32_t a;
    asm("{ .reg .u64 t; cvta.to.shared.u64 t, %1; cvt.u32.u64 %0, t; }" : "=r"(a) : "l"(p));
    return a;
}
__device__ __forceinline__ uint32_t elect_one_pred() {
    uint32_t pred;
    asm volatile("{\n\t.reg .pred p;\n\telect.sync _|p, 0xFFFFFFFF;\n\tselp.b32 %0, 1, 0, p;\n\t}" : "=r"(pred));
    return pred;
}
#define TCGEN05_ALLOC(a, n) asm volatile("tcgen05.alloc.cta_group::1.sync.aligned.shared::cta.b32 [%0], %1;" :: "r"((uint32_t)(a)), "r"((uint32_t)(n)) : "memory")
#define TCGEN05_DEALLOC(a, n) asm volatile("tcgen05.dealloc.cta_group::1.sync.aligned.b32 %0, %1;" :: "r"(a), "r"((uint32_t)(n)))
#define TCGEN05_RELINQ() asm volatile("tcgen05.relinquish_alloc_permit.cta_group::1.sync.aligned;")
#define TCGEN05_WAIT_ST() asm volatile("tcgen05.wait::st.sync.aligned;" ::: "memory")
#define TCGEN05_WAIT_LD() asm volatile("tcgen05.wait::ld.sync.aligned;" ::: "memory")
#define TCGEN05_FENCE_BEFORE() asm volatile("tcgen05.fence::before_thread_sync;" ::: "memory")
#define TCGEN05_FENCE_AFTER()  asm volatile("tcgen05.fence::after_thread_sync;" ::: "memory")
#define TCGEN05_COMMIT(m) asm volatile("tcgen05.commit.cta_group::1.mbarrier::arrive::one.shared::cluster.b64 [%0];" :: "r"((uint32_t)(m)) : "memory")
#define MBARRIER_INIT(m, c) asm volatile("mbarrier.init.shared.b64 [%0], %1;" :: "r"((uint32_t)(m)), "r"((uint32_t)(c)) : "memory")
#define MBARRIER_WAIT_PARITY(m, ph) do { \
    uint32_t _m = (uint32_t)(m), _p = (uint32_t)(ph), _d; \
    asm volatile("{\n\t.reg .pred p;\n\tmbarrier.try_wait.parity.acquire.cta.shared::cta.b64 p, [%1], %2;\n\tselp.b32 %0, 1, 0, p;\n\t}" : "=r"(_d) : "r"(_m), "r"(_p) : "memory"); \
    if (!_d) { asm volatile("{\n\t.reg .pred P1;\n\tWL_%=:\n\tmbarrier.try_wait.parity.acquire.cta.shared::cta.b64 P1, [%0], %1, 0x989680;\n\t@P1 bra.uni WD_%=;\n\tbra.uni WL_%=;\n\tWD_%=:\n\t}" :: "r"(_m), "r"(_p) : "memory"); } \
} while (0)
#define TCGEN05_MMA_F16(d, a, bd, id, en) do { \
    uint32_t _e = (en) ? 1 : 0, _z = 0; \
    asm volatile("{\n\t.reg .pred p;\n\tsetp.ne.u32 p, %6, 0;\n\ttcgen05.mma.cta_group::1.kind::f16 [%0], [%1], %2, %3, {%4, %4, %4, %4}, p;\n\t}" \
        :: "r"(d), "r"(a), "l"(bd), "r"(id), "r"(_z), "r"(_z), "r"(_e) : "memory"); \
} while (0)
#define TCGEN05_ST_X16(a, r) asm volatile("tcgen05.st.sync.aligned.32x32b.x16.b32 [%0], {%1,%2,%3,%4,%5,%6,%7,%8,%9,%10,%11,%12,%13,%14,%15,%16};" \
    :: "r"(a), "r"((r)[0]), "r"((r)[1]), "r"((r)[2]), "r"((r)[3]), "r"((r)[4]), "r"((r)[5]), "r"((r)[6]), "r"((r)[7]), \
       "r"((r)[8]), "r"((r)[9]), "r"((r)[10]), "r"((r)[11]), "r"((r)[12]), "r"((r)[13]), "r"((r)[14]), "r"((r)[15]) : "memory")
#define TCGEN05_LD_X32(r, a) asm volatile("tcgen05.ld.sync.aligned.32x32b.x32.b32 {%0,%1,%2,%3,%4,%5,%6,%7,%8,%9,%10,%11,%12,%13,%14,%15,%16,%17,%18,%19,%20,%21,%22,%23,%24,%25,%26,%27,%28,%29,%30,%31}, [%32];" \
    : "=r"((r)[0]), "=r"((r)[1]), "=r"((r)[2]), "=r"((r)[3]), "=r"((r)[4]), "=r"((r)[5]), "=r"((r)[6]), "=r"((r)[7]), \
      "=r"((r)[8]), "=r"((r)[9]), "=r"((r)[10]), "=r"((r)[11]), "=r"((r)[12]), "=r"((r)[13]), "=r"((r)[14]), "=r"((r)[15]), \
      "=r"((r)[16]), "=r"((r)[17]), "=r"((r)[18]), "=r"((r)[19]), "=r"((r)[20]), "=r"((r)[21]), "=r"((r)[22]), "=r"((r)[23]), \
      "=r"((r)[24]), "=r"((r)[25]), "=r"((r)[26]), "=r"((r)[27]), "=r"((r)[28]), "=r"((r)[29]), "=r"((r)[30]), "=r"((r)[31]) : "r"(a))
#define CP_ASYNC16(dst, src) asm volatile("cp.async.cg.shared.global [%0], [%1], 16;" :: "r"(dst), "l"(src) : "memory")
#define CP_COMMIT() asm volatile("cp.async.commit_group;" ::: "memory")
#define CP_WAIT0()  asm volatile("cp.async.wait_group 0;" ::: "memory")
#define CVT2(d, a, b) asm("cvt.rn.bf16x2.f32 %0, %1, %2;" : "=r"(d) : "f"(b), "f"(a))
static __device__ __forceinline__ uint64_t make_desc(uint32_t addr) {
    return ((uint64_t)2 << 61) | ((uint64_t)1 << 46) | ((uint64_t)64 << 32) | ((uint64_t)1 << 16)
         | ((uint64_t)(addr >> 4) & 0x3FFF);
}

// ---------------- device scratch ----------------
__device__ __align__(16) float g_HtH[64 * 64];
__device__ __align__(16) float g_A0[128 * 128];
__device__ __align__(16) float g_A[128 * 128];
__device__ __align__(16) float g_C[32 * 128];
__device__ __align__(16) float g_Ybuf[2][128 * 128];
__device__ __align__(16) float g_Zbuf[2][128 * 128];
__device__ __align__(16) float g_T[128 * 128];
__device__ float g_scal[4];
__device__ unsigned g_c1, g_c2, g_c3;
__device__ volatile unsigned g_s1, g_s2, g_s3;
__device__ __align__(16) unsigned char g_Wimg[W_IMG_BYTES];
// pre-converted activations: [tile][j=0..11][row=0..127][64 B]; j = c*2 + half
__device__ __align__(16) uint4 g_xbf[(size_t)MAX_TILES * 12 * 512];

// sense-reversing grid barrier (even #uses per launch -> replay-safe)
__device__ __forceinline__ void sbar(unsigned* cnt, volatile unsigned* sense,
                                     unsigned G, unsigned target) {
    __syncthreads();
    if (threadIdx.x == 0) {
        __threadfence();
        if (atomicAdd(cnt, 1u) == G - 1u) {
            *cnt = 0u;
            __threadfence();
            *sense = target;
        } else {
            while (*sense != target) { }
            __threadfence();
        }
    }
    __syncthreads();
}

#if TC_OK
// in-register 32x32 transpose: A[k] = V[lane][k] -> A[k] = V[k][lane]
__device__ __forceinline__ void transpose32(uint32_t* A, int lane) {
#pragma unroll
    for (int m = 1; m < 32; m <<= 1) {
#pragma unroll
        for (int k1 = 0; k1 < 32; k1++) {
            if (k1 & m) continue;
            int k2 = k1 | m;
            uint32_t sent = (lane & m) ? A[k1] : A[k2];
            uint32_t got = __shfl_xor_sync(0xFFFFFFFFu, sent, m);
            if (lane & m) A[k1] = got; else A[k2] = got;
        }
    }
}
__device__ __forceinline__ void epi512(uint32_t pd, int tile, int sub, int lane, int grp,
                                       float* __restrict__ dx, float* __restrict__ y) {
    size_t rbase = (size_t)tile * 128 + sub * 32;
    uint32_t r[32];
    TCGEN05_LD_X32(r, pd + (uint32_t)grp * 32);
    TCGEN05_WAIT_LD();
    transpose32(r, lane);
#pragma unroll
    for (int k = 0; k < 32; k++)
        dx[(rbase + k) * 128 + grp * 32 + lane] = __uint_as_float(r[k]);
    if (grp == 3) {
        TCGEN05_LD_X32(r, pd + 128);
        TCGEN05_WAIT_LD();
        transpose32(r, lane);
#pragma unroll
        for (int k = 0; k < 32; k++)
            y[(rbase + k) * 32 + lane] = __uint_as_float(r[k]);
    }
    TCGEN05_FENCE_BEFORE();
}
#endif

// ---------------- ONE fused kernel: setup + conversion + GEMM ----------------
__global__ void __launch_bounds__(512, 1) k_fused(
    const float* __restrict__ Q, const float* __restrict__ P,
    const float* __restrict__ S, const float* __restrict__ G,
    const float* __restrict__ H,
    const float* __restrict__ x, const float* __restrict__ u,
    float* __restrict__ dx, float* __restrict__ y, int ntiles) {
    extern __shared__ unsigned char smraw[];
    float* dyn = (float*)smraw;
    __shared__ float rowb[2][128];
    __shared__ float red[512];
    __shared__ float s_al[LAN_M], s_be[LAN_M + 1];
    __shared__ float sv[64], svp[64];
    __shared__ float l_lo, l_hi;
    __shared__ int l_flag[64];
    __shared__ uint32_t s_tptr;
    __shared__ __align__(8) unsigned long long s_mbar;
    int b = blockIdx.x, t = threadIdx.x;

#if TC_OK
    if (t < 32) { TCGEN05_ALLOC(smem_u32(&s_tptr), 512); TCGEN05_RELINQ(); }
    if (t == 0) MBARRIER_INIT(smem_u32(&s_mbar), 1);
#endif
    __syncthreads();

    if (b >= SET_CTAS) {
        // ===== activation pre-conversion (87 CTAs, barrier-free) =====
        float4* xs4 = (float4*)dyn;
        float4* us4 = xs4 + XS_F4;
        const float4* xg4 = (const float4*)x;
        const float4* ug4 = (const float4*)u;
        for (int tile = b - SET_CTAS; tile < ntiles; tile += CONV_CTAS) {
            size_t sb = (size_t)tile * 128;
            for (int i2 = t; i2 < 4096; i2 += 512) {
                int r = i2 >> 5, c4 = i2 & 31;
                xs4[r * 33 + c4] = xg4[((sb + r) << 5) + c4];
            }
            for (int i2 = t; i2 < 2048; i2 += 512) {
                int r = i2 >> 4, c4 = i2 & 15;
                us4[r * 17 + c4] = ug4[((sb + r) << 4) + c4];
            }
            __syncthreads();
            for (int job = t; job < 768; job += 512) {
                int r = job / 6, c = job % 6;
                uint32_t hi[16], lo[16];
#pragma unroll
                for (int q = 0; q < 8; q++) {
                    float4 v = (c < 4) ? xs4[r * 33 + c * 8 + q] : us4[r * 17 + (c - 4) * 8 + q];
                    uint32_t h0, h1;
                    CVT2(h0, v.x, v.y);
                    CVT2(h1, v.z, v.w);
                    hi[2 * q] = h0; hi[2 * q + 1] = h1;
                    float rx = v.x - __uint_as_float(h0 << 16);
                    float ry = v.y - __uint_as_float(h0 & 0xFFFF0000u);
                    float rz = v.z - __uint_as_float(h1 << 16);
                    float rw = v.w - __uint_as_float(h1 & 0xFFFF0000u);
                    uint32_t l0, l1;
                    CVT2(l0, rx, ry);
                    CVT2(l1, rz, rw);
                    lo[2 * q] = l0; lo[2 * q + 1] = l1;
                }
                uint4* dhi = g_xbf + ((size_t)tile * 12 + c * 2) * 512 + r * 4;
                uint4* dlo = dhi + 512;
#pragma unroll
                for (int q4 = 0; q4 < 4; q4++) {
                    dhi[q4] = make_uint4(hi[4 * q4], hi[4 * q4 + 1], hi[4 * q4 + 2], hi[4 * q4 + 3]);
                    dlo[q4] = make_uint4(lo[4 * q4], lo[4 * q4 + 1], lo[4 * q4 + 2], lo[4 * q4 + 3]);
                }
            }
            __syncthreads();
        }
    } else {
        // ===== setup path (CTAs 0..64), barrier group = SET_CTAS =====
        float* sA = dyn;
        float* sZ = dyn + 16384;
        // 1a: HtH (b<8), A0 (8..39), power-iteration lam_max(Q) (b==63)
        if (b < 8) {
            int e = b * 512 + t, i = e >> 6, j = e & 63;
            float s = 0.f;
#pragma unroll 8
            for (int k = 0; k < 128; k++) s += H[k * 64 + i] * H[k * 64 + j];
            g_HtH[e] = s;
        } else if (b < 40) {
            int e = (b - 8) * 512 + t, i = e >> 7, j = e & 127;
            float s = 0.f;
#pragma unroll
            for (int k = 0; k < 32; k++) s += G[k * 128 + i] * G[k * 128 + j];
            g_A0[e] = -0.5f * (Q[e] + s + ((i == j) ? EPSc : 0.f)) + S[e];
        } else if (b == 63) {
            // power iteration for c = lam_max(Q); padded stride 132 (bank-safe)
            float* sQ = dyn;                       // 128*132 floats < 32768 cap
            for (int q2 = t; q2 < 16384; q2 += 512) {
                int r = q2 >> 7, k = q2 & 127;
                sQ[r * 132 + k] = Q[q2];
            }
            float* pv = rowb[0];
            if (t < 128) pv[t] = 1.f;
            __syncthreads();
            float lam = 1.f;
            for (int itp = 0; itp < 8; itp++) {
                float w = 0.f;
                if (t < 128) {
                    const float* qr = &sQ[t * 132];
                    float a0 = 0.f, a1 = 0.f, a2 = 0.f, a3 = 0.f;
#pragma unroll 8
                    for (int k = 0; k < 128; k += 4) {
                        a0 += qr[k] * pv[k];
                        a1 += qr[k + 1] * pv[k + 1];
                        a2 += qr[k + 2] * pv[k + 2];
                        a3 += qr[k + 3] * pv[k + 3];
                    }
                    w = (a0 + a1) + (a2 + a3);
                }
                red[t] = (t < 128) ? w * w : 0.f;
                __syncthreads();
                for (int o = 256; o > 0; o >>= 1) { if (t < o) red[t] += red[t + o]; __syncthreads(); }
                float nrm = sqrtf(red[0]);
                __syncthreads();
                if (t < 128) pv[t] = w / nrm;
                lam = nrm;                       // ||Q v||, v normalized -> -> lam_max
                __syncthreads();
            }
            if (t == 0) {
                float c = lam;
                if (c < 1e-10f) c = 1e-10f;
                g_scal[0] = 1.f / c;
                g_scal[2] = c;
            }
        }
        sbar(&g_c1, &g_s1, SET_CTAS, 1u);

        // 1b: A = A0@P (b<32), C = G@P (32..39), Y0 (40..47), Z0 (48..55)
        if (b < 32) {
            int e = b * 512 + t, i = e >> 7, j = e & 127;
            const float* a0 = &g_A0[i * 128];
            float s = 0.f;
#pragma unroll 8
            for (int k = 0; k < 128; k++) s += __ldcg(a0 + k) * P[k * 128 + j];
            g_A[e] = s;
        } else if (b < 40) {
            int e = (b - 32) * 512 + t, i = e >> 7, j = e & 127;
            float s = 0.f;
#pragma unroll 8
            for (int k = 0; k < 128; k++) s += G[i * 128 + k] * P[k * 128 + j];
            g_C[e] = s;
        } else if (b < 48) {
            float ic = __ldcg(&g_scal[0]);
            int base = (b - 40) * 2048 + t;
#pragma unroll
            for (int r = 0; r < 4; r++) g_Ybuf[0][base + r * 512] = Q[base + r * 512] * ic;
        } else if (b < 56) {
            int base = (b - 48) * 2048 + t;
#pragma unroll
            for (int r = 0; r < 4; r++) { int e = base + r * 512; g_Zbuf[0][e] = ((e >> 7) == (e & 127)) ? 1.f : 0.f; }
        }
        sbar(&g_c1, &g_s1, SET_CTAS, 0u);

        // phase 2: NS (CTAs 0..63) || warp-Lanczos (CTA 64)
        if (b < NSC) {
            unsigned s2 = 0;
            int p = 0;
            int half = t >> 8, tt = t & 255;
            int i = tt >> 7, j = tt & 127;
            int r0 = b * 2;
            for (int it = 0; it < NS_ITERS; it++) {
                const float* Y = g_Ybuf[p];
                const float* Z = g_Zbuf[p];
                float* Yn = g_Ybuf[p ^ 1];
                float* Zn = g_Zbuf[p ^ 1];
                if (half == 0) {
                    for (int q = tt; q < 4096; q += 256) ((float4*)sA)[q] = __ldcg(((const float4*)Y) + q);
                    rowb[i][j] = __ldcg(&Z[(r0 + i) * 128 + j]);
                } else {
                    for (int q = tt; q < 4096; q += 256) ((float4*)sZ)[q] = __ldcg(((const float4*)Z) + q);
                }
                __syncthreads();
                if (half == 0) {
                    const float* rw = rowb[i];
                    float s = 0.f;
#pragma unroll 8
                    for (int k = 0; k < 128; k++) s += rw[k] * sA[k * 128 + j];
                    g_T[(r0 + i) * 128 + j] = (((r0 + i) == j) ? 1.5f : 0.f) - 0.5f * s;
                }
                s2 ^= 1; sbar(&g_c2, &g_s2, NSC, s2);
                for (int q = t; q < 4096; q += 512)
                    ((float4*)sA)[q] = __ldcg(((const float4*)g_T) + q);
                if (half == 0) rowb[i][j] = __ldcg(&Y[(r0 + i) * 128 + j]);
                __syncthreads();
                if (half == 0) {
                    const float* rw = rowb[i];
                    float s = 0.f;
#pragma unroll 8
                    for (int k = 0; k < 128; k++) s += rw[k] * sA[k * 128 + j];
                    Yn[(r0 + i) * 128 + j] = s;
                } else {
                    const float* tr = &sA[(r0 + i) * 128];
                    float s = 0.f;
#pragma unroll 8
                    for (int k = 0; k < 128; k++) s += tr[k] * sZ[k * 128 + j];
                    Zn[(r0 + i) * 128 + j] = s;
                }
                s2 ^= 1; sbar(&g_c2, &g_s2, NSC, s2);
                __syncthreads();
                p ^= 1;
            }
        } else {
            // Lanczos lam_max(HtH), one warp, shfl reductions
            float* sM = sA;
            for (int q = t; q < 4096; q += 512) sM[q] = __ldcg(&g_HtH[q]);
            __syncthreads();
            if (t < 32) {
                int l2 = t * 2;
                float r0 = 0.f, r1 = 0.f;
#pragma unroll 8
                for (int k = 0; k < 64; k++) { r0 += sM[l2 * 64 + k]; r1 += sM[(l2 + 1) * 64 + k]; }
                float nn = r0 * r0 + r1 * r1;
#pragma unroll
                for (int o = 16; o > 0; o >>= 1) nn += __shfl_xor_sync(0xFFFFFFFFu, nn, o);
                float inv = rsqrtf(nn);
                sv[l2] = r0 * inv; sv[l2 + 1] = r1 * inv;
                svp[l2] = 0.f; svp[l2 + 1] = 0.f;
                if (t == 0) s_be[0] = 0.f;
                float bprev = 0.f;
                for (int jj = 0; jj < LAN_M; jj++) {
                    __syncwarp();
                    float w0 = 0.f, w1 = 0.f;
#pragma unroll 8
                    for (int k = 0; k < 64; k++) {
                        float vk = sv[k];
                        w0 += sM[l2 * 64 + k] * vk;
                        w1 += sM[(l2 + 1) * 64 + k] * vk;
                    }
                    w0 -= bprev * svp[l2];
                    w1 -= bprev * svp[l2 + 1];
                    float ap = w0 * sv[l2] + w1 * sv[l2 + 1];
#pragma unroll
                    for (int o = 16; o > 0; o >>= 1) ap += __shfl_xor_sync(0xFFFFFFFFu, ap, o);
                    w0 -= ap * sv[l2]; w1 -= ap * sv[l2 + 1];
                    float b2 = w0 * w0 + w1 * w1;
#pragma unroll
                    for (int o = 16; o > 0; o >>= 1) b2 += __shfl_xor_sync(0xFFFFFFFFu, b2, o);
                    float bn = sqrtf(b2);
                    if (t == 0) { s_al[jj] = ap; s_be[jj + 1] = bn; }
                    svp[l2] = sv[l2]; svp[l2 + 1] = sv[l2 + 1];
                    float ib = (bn > 1e-12f) ? (1.f / bn) : 0.f;
                    __syncwarp();
                    sv[l2] = w0 * ib; sv[l2 + 1] = w1 * ib;
                    bprev = bn;
                }
            }
            __syncthreads();
            if (t == 0) {
                float hi = 0.f;
                for (int jj = 0; jj < LAN_M; jj++) {
                    float g = s_al[jj] + fabsf(s_be[jj]) + fabsf(s_be[jj + 1]);
                    if (g > hi) hi = g;
                }
                l_lo = 0.f; l_hi = hi + 1.f;
            }
            __syncthreads();
            for (int r = 0; r < 5; r++) {
                float lo = l_lo, hi = l_hi;
                if (t < 64) {
                    float xm = lo + (hi - lo) * (float)(t + 1) * (1.f / 65.f);
                    int cnt = 0; float d = 1.f;
                    for (int jj = 0; jj < LAN_M; jj++) {
                        float bj = (jj == 0) ? 0.f : s_be[jj];
                        d = (s_al[jj] - xm) - __fdividef(bj * bj, d);
                        if (d == 0.f) d = -1e-30f;
                        if (d < 0.f) cnt++;
                    }
                    l_flag[t] = (cnt >= LAN_M) ? 1 : 0;
                }
                __syncthreads();
                if (t == 0) {
                    float nlo = lo, nhi = hi;
                    for (int q = 0; q < 64; q++) {
                        float sq = lo + (hi - lo) * (float)(q + 1) * (1.f / 65.f);
                        if (l_flag[q]) { nhi = sq; break; }
                        nlo = sq;
                    }
                    l_lo = nlo; l_hi = nhi;
                }
                __syncthreads();
            }
            if (t == 0) {
                float lam = 0.5f * (l_lo + l_hi);
                if (lam < 1e-20f) lam = 1e-20f;
                float cfro = __ldcg(&g_scal[2]);
                g_scal[1] = sqrtf(cfro) / (1.01f * sqrtf(lam));
            }
        }
        sbar(&g_c1, &g_s1, SET_CTAS, 1u);

        // phase 3: packW (B inline)
        {
            int idx = b * 512 + t;
            if (idx < 30720) {
                int o = idx / 192, k = idx % 192;
                float v;
                if (k < 128) {
                    v = (o < 128) ? __ldcg(&g_A[o * 128 + k]) : __ldcg(&g_C[(o - 128) * 128 + k]);
                } else if (o < 128) {
                    const float* yr = &g_Ybuf[0][o * 128];
                    int j = k - 128;
                    float s0 = 0.f, s1 = 0.f;
#pragma unroll 4
                    for (int kk = 0; kk < 128; kk += 2) {
                        s0 += __ldcg(yr + kk) * H[kk * 64 + j];
                        s1 += __ldcg(yr + kk + 1) * H[(kk + 1) * 64 + j];
                    }
                    v = (s0 + s1) * __ldcg(&g_scal[1]);
                } else {
                    v = 0.f;
                }
                __nv_bfloat16 h = __float2bfloat16_rn(v);
                __nv_bfloat16 l = __float2bfloat16_rn(v - __bfloat162float(h));
                uint32_t boff = (uint32_t)(((o >> 3) + (k >> 6) * 20) * 1024 + (o & 7) * 128 + (k & 63) * 2);
                uint32_t sw = boff ^ ((boff >> 3) & 0x70);
                *(unsigned short*)(g_Wimg + sw) = __bfloat16_as_ushort(h);
                *(unsigned short*)(g_Wimg + W_IMG_HALF + sw) = __bfloat16_as_ushort(l);
            }
        }
        sbar(&g_c1, &g_s1, SET_CTAS, 0u);
    }

    // ===== global join: all 152 CTAs =====
    sbar(&g_c3, &g_s3, GRID, 1u);

#if TC_OK
    // ===== GEMM persistent loop =====
    {
        int wid = t >> 5;
        int sub = wid & 3;
        int grp = wid >> 2;
        int lane = t & 31;
        uint32_t smbase = smem_u32(smraw);
        uint32_t wbase = (smbase + 1023u) & ~1023u;
        unsigned char* wptr = smraw + (wbase - smbase);
        unsigned char* aslots = wptr + W_IMG_BYTES;
        {
            const float4* src = (const float4*)g_Wimg;
            float4* dst = (float4*)wptr;
            for (int i = t; i < W_IMG_BYTES / 16; i += 512) dst[i] = src[i];
        }
        __syncthreads();
        uint32_t tb = s_tptr;
        uint32_t mb = smem_u32(&s_mbar);
        uint64_t descH = make_desc(wbase);
        uint64_t descL = make_desc(wbase + W_IMG_HALF);
        uint32_t wofs = (uint32_t)sub << 21;
        uint32_t parity = 0;
        int prev = -1;
        int buf = 0, prevbuf = 0;

        uint32_t slotWarp[3];
        uint32_t tcol[3];
        int jarr[3];
#pragma unroll
        for (int k = 0; k < 3; k++) {
            int j = grp + 4 * k;
            jarr[k] = j;
            int c = j >> 1, half = j & 1;
            slotWarp[k] = smem_u32(aslots + (wid * 3 + k) * 2048);
            tcol[k] = (uint32_t)(half * 96 + c * 16);
        }
        uint32_t loff = (uint32_t)lane * 16;

        if (b < ntiles) {
#pragma unroll
            for (int k = 0; k < 3; k++) {
                const char* gb = (const char*)g_xbf +
                    (((size_t)b * 12 + jarr[k]) * 8192) + sub * 2048;
#pragma unroll
                for (int q = 0; q < 4; q++)
                    CP_ASYNC16(slotWarp[k] + q * 512 + loff, gb + q * 512 + loff);
            }
        }
        CP_COMMIT();

        for (int tile = b; tile < ntiles; tile += GRID) {
            if (prev >= 0) { MBARRIER_WAIT_PARITY(mb, parity); parity ^= 1; TCGEN05_FENCE_AFTER(); }
            CP_WAIT0();
            __syncwarp();
#pragma unroll
            for (int k = 0; k < 3; k++) {
                const uint4* sp = (const uint4*)(aslots + (wid * 3 + k) * 2048 + lane * 64);
                uint4 a0 = sp[0], a1 = sp[1], a2 = sp[2], a3 = sp[3];
                uint32_t pk[16] = {a0.x, a0.y, a0.z, a0.w, a1.x, a1.y, a1.z, a1.w,
                                   a2.x, a2.y, a2.z, a2.w, a3.x, a3.y, a3.z, a3.w};
                TCGEN05_ST_X16(tb + tcol[k] + wofs, pk);
            }
            TCGEN05_WAIT_ST();
            TCGEN05_FENCE_BEFORE();
            __syncthreads();
            uint32_t dcol = tb + 192u + (uint32_t)buf * 160u;
            if (t < 32) {
                TCGEN05_FENCE_AFTER();
                if (elect_one_pred()) {
                    int idx = 0;
#pragma unroll
                    for (int term = 0; term < 3; term++) {
                        uint32_t ab = tb + ((term == 2) ? 96u : 0u);
                        uint64_t bd = (term == 1) ? descL : descH;
#pragma unroll
                        for (int k = 0; k < 12; k++) {
                            uint64_t d = bd + (uint64_t)((k >> 2) * 1280 + (k & 3) * 2);
                            TCGEN05_MMA_F16(dcol, ab + (uint32_t)(k * 8), d, IDESC_MAIN, idx > 0);
                            idx++;
                        }
                    }
                    TCGEN05_COMMIT(mb);
                }
            }
            int nxt = tile + GRID;
            if (nxt < ntiles) {
#pragma unroll
                for (int k = 0; k < 3; k++) {
                    const char* gb = (const char*)g_xbf +
                        (((size_t)nxt * 12 + jarr[k]) * 8192) + sub * 2048;
#pragma unroll
                    for (int q = 0; q < 4; q++)
                        CP_ASYNC16(slotWarp[k] + q * 512 + loff, gb + q * 512 + loff);
                }
            }
            CP_COMMIT();
            if (prev >= 0)
                epi512(tb + 192u + (uint32_t)prevbuf * 160u, prev, sub, lane, grp, dx, y);
            prev = tile;
            prevbuf = buf;
            buf ^= 1;
        }
        if (prev >= 0) {
            MBARRIER_WAIT_PARITY(mb, parity); parity ^= 1;
            TCGEN05_FENCE_AFTER();
            epi512(tb + 192u + (uint32_t)prevbuf * 160u, prev, sub, lane, grp, dx, y);
        }
        __syncthreads();
        if (t < 32) TCGEN05_DEALLOC(tb, 512);
    }
#else
    // Generic-PTX fallback (never executed on GB300).
    for (int tile = b; tile < ntiles; tile += GRID) {
        for (int rr = t; rr < 128; rr += 512) {
            size_t s = (size_t)tile * 128 + rr;
            const float* xr = &x[s * 128];
            for (int o = 0; o < 128; o++) {
                float acc = 0.f;
                for (int k = 0; k < 128; k++) acc += xr[k] * g_A[o * 128 + k];
                dx[s * 128 + o] = acc;
            }
            for (int o = 0; o < 32; o++) {
                float acc = 0.f;
                for (int k = 0; k < 128; k++) acc += xr[k] * g_C[o * 128 + k];
                y[s * 32 + o] = acc;
            }
        }
    }
#endif

    // final join: returns g_s3 to 0 for replay-safety
    sbar(&g_c3, &g_s3, GRID, 0u);
}

// ---------------- launcher (single launch) ----------------
extern "C" void kernel_launch(void* const* d_in, const int* in_sizes, int n_in,
                              void* d_out, int out_size) {
    const float* u = (const float*)d_in[0];
    const float* x = (const float*)d_in[1];
    const float* Q = (const float*)d_in[2];
    const float* P = (const float*)d_in[3];
    const float* S = (const float*)d_in[4];
    const float* G = (const float*)d_in[5];
    const float* H = (const float*)d_in[6];
    int N = in_sizes[0] / 64;
    float* dx = (float*)d_out;
    float* y = dx + (size_t)N * 128;
    int ntiles = N / 128;
    if (ntiles > MAX_TILES) ntiles = MAX_TILES;

    int smem = 1024 + W_IMG_BYTES + 48 * 2048;
    cudaFuncSetAttribute(k_fused, cudaFuncAttributeMaxDynamicSharedMemorySize, smem);
    k_fused<<<GRID, 512, smem>>>(Q, P, S, G, H, x, u, dx, y, ntiles);
}

// round 15
// speedup vs baseline: 1.3001x; 1.3001x over previous
#include <cuda_runtime.h>
#include <cuda_bf16.h>
#include <math.h>
#include <stdint.h>

#define NS_ITERS 12
#define LAN_M 32
#define EPSc 1e-4f
#define IDESC_MAIN 0x8280490u   // f32 accum, bf16 a/b, M=128, N=160
#define W_IMG_HALF 61440
#define W_IMG_BYTES 122880
#define XS_F4 (128 * 33)
#define US_F4 (128 * 17)
#define GRID 152
#define SET_CTAS 65
#define NSC 64
#define CONV_CTAS (GRID - SET_CTAS)
#define MAX_TILES 2048

#if !defined(__CUDA_ARCH__) || defined(__CUDA_ARCH_FEAT_SM103_ALL) || defined(__CUDA_ARCH_FEAT_SM100_ALL)
#define TC_OK 1
#else
#define TC_OK 0
#endif

// ---------------- PTX helpers ----------------
__device__ __forceinline__ uint32_t smem_u32(const void* p) {
    uint32_t a;
    asm("{ .reg .u64 t; cvta.to.shared.u64 t, %1; cvt.u32.u64 %0, t; }" : "=r"(a) : "l"(p));
    return a;
}
__device__ __forceinline__ uint32_t elect_one_pred() {
    uint32_t pred;
    asm volatile("{\n\t.reg .pred p;\n\telect.sync _|p, 0xFFFFFFFF;\n\tselp.b32 %0, 1, 0, p;\n\t}" : "=r"(pred));
    return pred;
}
#define TCGEN05_ALLOC(a, n) asm volatile("tcgen05.alloc.cta_group::1.sync.aligned.shared::cta.b32 [%0], %1;" :: "r"((uint32_t)(a)), "r"((uint32_t)(n)) : "memory")
#define TCGEN05_DEALLOC(a, n) asm volatile("tcgen05.dealloc.cta_group::1.sync.aligned.b32 %0, %1;" :: "r"(a), "r"((uint32_t)(n)))
#define TCGEN05_RELINQ() asm volatile("tcgen05.relinquish_alloc_permit.cta_group::1.sync.aligned;")
#define TCGEN05_WAIT_ST() asm volatile("tcgen05.wait::st.sync.aligned;" ::: "memory")
#define TCGEN05_WAIT_LD() asm volatile("tcgen05.wait::ld.sync.aligned;" ::: "memory")
#define TCGEN05_FENCE_BEFORE() asm volatile("tcgen05.fence::before_thread_sync;" ::: "memory")
#define TCGEN05_FENCE_AFTER()  asm volatile("tcgen05.fence::after_thread_sync;" ::: "memory")
#define TCGEN05_COMMIT(m) asm volatile("tcgen05.commit.cta_group::1.mbarrier::arrive::one.shared::cluster.b64 [%0];" :: "r"((uint32_t)(m)) : "memory")
#define MBARRIER_INIT(m, c) asm volatile("mbarrier.init.shared.b64 [%0], %1;" :: "r"((uint32_t)(m)), "r"((uint32_t)(c)) : "memory")
#define MBARRIER_WAIT_PARITY(m, ph) do { \
    uint32_t _m = (uint32_t)(m), _p = (uint32_t)(ph), _d; \
    asm volatile("{\n\t.reg .pred p;\n\tmbarrier.try_wait.parity.acquire.cta.shared::cta.b64 p, [%1], %2;\n\tselp.b32 %0, 1, 0, p;\n\t}" : "=r"(_d) : "r"(_m), "r"(_p) : "memory"); \
    if (!_d) { asm volatile("{\n\t.reg .pred P1;\n\tWL_%=:\n\tmbarrier.try_wait.parity.acquire.cta.shared::cta.b64 P1, [%0], %1, 0x989680;\n\t@P1 bra.uni WD_%=;\n\tbra.uni WL_%=;\n\tWD_%=:\n\t}" :: "r"(_m), "r"(_p) : "memory"); } \
} while (0)
#define TCGEN05_MMA_F16(d, a, bd, id, en) do { \
    uint32_t _e = (en) ? 1 : 0, _z = 0; \
    asm volatile("{\n\t.reg .pred p;\n\tsetp.ne.u32 p, %6, 0;\n\ttcgen05.mma.cta_group::1.kind::f16 [%0], [%1], %2, %3, {%4, %4, %4, %4}, p;\n\t}" \
        :: "r"(d), "r"(a), "l"(bd), "r"(id), "r"(_z), "r"(_z), "r"(_e) : "memory"); \
} while (0)
#define TCGEN05_ST_X16(a, r) asm volatile("tcgen05.st.sync.aligned.32x32b.x16.b32 [%0], {%1,%2,%3,%4,%5,%6,%7,%8,%9,%10,%11,%12,%13,%14,%15,%16};" \
    :: "r"(a), "r"((r)[0]), "r"((r)[1]), "r"((r)[2]), "r"((r)[3]), "r"((r)[4]), "r"((r)[5]), "r"((r)[6]), "r"((r)[7]), \
       "r"((r)[8]), "r"((r)[9]), "r"((r)[10]), "r"((r)[11]), "r"((r)[12]), "r"((r)[13]), "r"((r)[14]), "r"((r)[15]) : "memory")
#define TCGEN05_LD_X32(r, a) asm volatile("tcgen05.ld.sync.aligned.32x32b.x32.b32 {%0,%1,%2,%3,%4,%5,%6,%7,%8,%9,%10,%11,%12,%13,%14,%15,%16,%17,%18,%19,%20,%21,%22,%23,%24,%25,%26,%27,%28,%29,%30,%31}, [%32];" \
    : "=r"((r)[0]), "=r"((r)[1]), "=r"((r)[2]), "=r"((r)[3]), "=r"((r)[4]), "=r"((r)[5]), "=r"((r)[6]), "=r"((r)[7]), \
      "=r"((r)[8]), "=r"((r)[9]), "=r"((r)[10]), "=r"((r)[11]), "=r"((r)[12]), "=r"((r)[13]), "=r"((r)[14]), "=r"((r)[15]), \
      "=r"((r)[16]), "=r"((r)[17]), "=r"((r)[18]), "=r"((r)[19]), "=r"((r)[20]), "=r"((r)[21]), "=r"((r)[22]), "=r"((r)[23]), \
      "=r"((r)[24]), "=r"((r)[25]), "=r"((r)[26]), "=r"((r)[27]), "=r"((r)[28]), "=r"((r)[29]), "=r"((r)[30]), "=r"((r)[31]) : "r"(a))
#define CP_ASYNC16(dst, src) asm volatile("cp.async.cg.shared.global [%0], [%1], 16;" :: "r"(dst), "l"(src) : "memory")
#define CP_COMMIT() asm volatile("cp.async.commit_group;" ::: "memory")
#define CP_WAIT0()  asm volatile("cp.async.wait_group 0;" ::: "memory")
#define CVT2(d, a, b) asm("cvt.rn.bf16x2.f32 %0, %1, %2;" : "=r"(d) : "f"(b), "f"(a))
static __device__ __forceinline__ uint64_t make_desc(uint32_t addr) {
    return ((uint64_t)2 << 61) | ((uint64_t)1 << 46) | ((uint64_t)64 << 32) | ((uint64_t)1 << 16)
         | ((uint64_t)(addr >> 4) & 0x3FFF);
}

// ---------------- device scratch ----------------
__device__ __align__(16) float g_HtH[64 * 64];
__device__ __align__(16) float g_A0[128 * 128];
__device__ __align__(16) float g_A[128 * 128];
__device__ __align__(16) float g_C[32 * 128];
__device__ __align__(16) float g_Ybuf[2][128 * 128];
__device__ __align__(16) float g_Zbuf[2][128 * 128];
__device__ __align__(16) float g_T[128 * 128];
__device__ float g_scal[4];
__device__ unsigned g_c1, g_c2, g_c3;
__device__ volatile unsigned g_s1, g_s2, g_s3;
__device__ __align__(16) unsigned char g_Wimg[W_IMG_BYTES];
// pre-converted activations: plane (tile, j), j = c*2 + half; plane layout [q=0..3][row=0..127][16B]
__device__ __align__(16) uint4 g_xbf[(size_t)MAX_TILES * 12 * 512];

// sense-reversing grid barrier (even #uses per launch -> replay-safe)
__device__ __forceinline__ void sbar(unsigned* cnt, volatile unsigned* sense,
                                     unsigned G, unsigned target) {
    __syncthreads();
    if (threadIdx.x == 0) {
        __threadfence();
        if (atomicAdd(cnt, 1u) == G - 1u) {
            *cnt = 0u;
            __threadfence();
            *sense = target;
        } else {
            while (*sense != target) { }
            __threadfence();
        }
    }
    __syncthreads();
}

#if TC_OK
// in-register 32x32 transpose: A[k] = V[lane][k] -> A[k] = V[k][lane]
__device__ __forceinline__ void transpose32(uint32_t* A, int lane) {
#pragma unroll
    for (int m = 1; m < 32; m <<= 1) {
#pragma unroll
        for (int k1 = 0; k1 < 32; k1++) {
            if (k1 & m) continue;
            int k2 = k1 | m;
            uint32_t sent = (lane & m) ? A[k1] : A[k2];
            uint32_t got = __shfl_xor_sync(0xFFFFFFFFu, sent, m);
            if (lane & m) A[k1] = got; else A[k2] = got;
        }
    }
}
__device__ __forceinline__ void epi512(uint32_t pd, int tile, int sub, int lane, int grp,
                                       float* __restrict__ dx, float* __restrict__ y) {
    size_t rbase = (size_t)tile * 128 + sub * 32;
    uint32_t r[32];
    TCGEN05_LD_X32(r, pd + (uint32_t)grp * 32);
    TCGEN05_WAIT_LD();
    transpose32(r, lane);
#pragma unroll
    for (int k = 0; k < 32; k++)
        dx[(rbase + k) * 128 + grp * 32 + lane] = __uint_as_float(r[k]);
    if (grp == 3) {
        TCGEN05_LD_X32(r, pd + 128);
        TCGEN05_WAIT_LD();
        transpose32(r, lane);
#pragma unroll
        for (int k = 0; k < 32; k++)
            y[(rbase + k) * 32 + lane] = __uint_as_float(r[k]);
    }
    TCGEN05_FENCE_BEFORE();
}
#endif

// ---------------- ONE fused kernel: setup + conversion + GEMM ----------------
__global__ void __launch_bounds__(512, 1) k_fused(
    const float* __restrict__ Q, const float* __restrict__ P,
    const float* __restrict__ S, const float* __restrict__ G,
    const float* __restrict__ H,
    const float* __restrict__ x, const float* __restrict__ u,
    float* __restrict__ dx, float* __restrict__ y, int ntiles) {
    extern __shared__ unsigned char smraw[];
    float* dyn = (float*)smraw;
    __shared__ float rowb[2][128];
    __shared__ float red[512];
    __shared__ float s_al[LAN_M], s_be[LAN_M + 1];
    __shared__ float sv[64], svp[64];
    __shared__ float l_lo, l_hi;
    __shared__ int l_flag[64];
    __shared__ uint32_t s_tptr;
    __shared__ __align__(8) unsigned long long s_mbar;
    int b = blockIdx.x, t = threadIdx.x;

#if TC_OK
    if (t < 32) { TCGEN05_ALLOC(smem_u32(&s_tptr), 512); TCGEN05_RELINQ(); }
    if (t == 0) MBARRIER_INIT(smem_u32(&s_mbar), 1);
#endif
    __syncthreads();

    if (b >= SET_CTAS) {
        // ===== activation pre-conversion (87 CTAs, barrier-free, coalesced stores) =====
        float4* xs4 = (float4*)dyn;
        float4* us4 = xs4 + XS_F4;
        const float4* xg4 = (const float4*)x;
        const float4* ug4 = (const float4*)u;
        int wid = t >> 5, lane = t & 31;
        for (int tile = b - SET_CTAS; tile < ntiles; tile += CONV_CTAS) {
            size_t sb = (size_t)tile * 128;
            for (int i2 = t; i2 < 4096; i2 += 512) {
                int r = i2 >> 5, c4 = i2 & 31;
                xs4[r * 33 + c4] = xg4[((sb + r) << 5) + c4];
            }
            for (int i2 = t; i2 < 2048; i2 += 512) {
                int r = i2 >> 4, c4 = i2 & 15;
                us4[r * 17 + c4] = ug4[((sb + r) << 4) + c4];
            }
            __syncthreads();
            // warp-jobs: wj = (rb, c); lane = row within rb block -> coalesced plane stores
            for (int wj = wid; wj < 24; wj += 16) {
                int c = wj % 6, rb = wj / 6;
                int r = rb * 32 + lane;
                uint32_t hi[16], lo[16];
#pragma unroll
                for (int q = 0; q < 8; q++) {
                    float4 v = (c < 4) ? xs4[r * 33 + c * 8 + q] : us4[r * 17 + (c - 4) * 8 + q];
                    uint32_t h0, h1;
                    CVT2(h0, v.x, v.y);
                    CVT2(h1, v.z, v.w);
                    hi[2 * q] = h0; hi[2 * q + 1] = h1;
                    float rx = v.x - __uint_as_float(h0 << 16);
                    float ry = v.y - __uint_as_float(h0 & 0xFFFF0000u);
                    float rz = v.z - __uint_as_float(h1 << 16);
                    float rw = v.w - __uint_as_float(h1 & 0xFFFF0000u);
                    uint32_t l0, l1;
                    CVT2(l0, rx, ry);
                    CVT2(l1, rz, rw);
                    lo[2 * q] = l0; lo[2 * q + 1] = l1;
                }
                // plane layout: [q][row][16B]; lanes contiguous -> 4 lines per STG.128
                uint4* phi = g_xbf + ((size_t)tile * 12 + c * 2) * 512;
                uint4* plo = phi + 512;
#pragma unroll
                for (int q4 = 0; q4 < 4; q4++) {
                    phi[q4 * 128 + r] = make_uint4(hi[4 * q4], hi[4 * q4 + 1], hi[4 * q4 + 2], hi[4 * q4 + 3]);
                    plo[q4 * 128 + r] = make_uint4(lo[4 * q4], lo[4 * q4 + 1], lo[4 * q4 + 2], lo[4 * q4 + 3]);
                }
            }
            __syncthreads();
        }
    } else {
        // ===== setup path (CTAs 0..64), barrier group = SET_CTAS =====
        float* sA = dyn;
        float* sZ = dyn + 16384;
        // 1a: HtH (b<8), A0 (8..39), power-iteration lam_max(Q) (b==63)
        if (b < 8) {
            int e = b * 512 + t, i = e >> 6, j = e & 63;
            float s = 0.f;
#pragma unroll 8
            for (int k = 0; k < 128; k++) s += H[k * 64 + i] * H[k * 64 + j];
            g_HtH[e] = s;
        } else if (b < 40) {
            int e = (b - 8) * 512 + t, i = e >> 7, j = e & 127;
            float s = 0.f;
#pragma unroll
            for (int k = 0; k < 32; k++) s += G[k * 128 + i] * G[k * 128 + j];
            g_A0[e] = -0.5f * (Q[e] + s + ((i == j) ? EPSc : 0.f)) + S[e];
        } else if (b == 63) {
            float* sQ = dyn;                       // 128*132 floats
            for (int q2 = t; q2 < 16384; q2 += 512) {
                int r = q2 >> 7, k = q2 & 127;
                sQ[r * 132 + k] = Q[q2];
            }
            float* pv = rowb[0];
            if (t < 128) pv[t] = 1.f;
            __syncthreads();
            float lam = 1.f;
            for (int itp = 0; itp < 8; itp++) {
                float w = 0.f;
                if (t < 128) {
                    const float* qr = &sQ[t * 132];
                    float a0 = 0.f, a1 = 0.f, a2 = 0.f, a3 = 0.f;
#pragma unroll 8
                    for (int k = 0; k < 128; k += 4) {
                        a0 += qr[k] * pv[k];
                        a1 += qr[k + 1] * pv[k + 1];
                        a2 += qr[k + 2] * pv[k + 2];
                        a3 += qr[k + 3] * pv[k + 3];
                    }
                    w = (a0 + a1) + (a2 + a3);
                }
                red[t] = (t < 128) ? w * w : 0.f;
                __syncthreads();
                for (int o = 256; o > 0; o >>= 1) { if (t < o) red[t] += red[t + o]; __syncthreads(); }
                float nrm = sqrtf(red[0]);
                __syncthreads();
                if (t < 128) pv[t] = w / nrm;
                lam = nrm;
                __syncthreads();
            }
            if (t == 0) {
                float c = lam;
                if (c < 1e-10f) c = 1e-10f;
                g_scal[0] = 1.f / c;
                g_scal[2] = c;
            }
        }
        sbar(&g_c1, &g_s1, SET_CTAS, 1u);

        // 1b: A = A0@P (b<32), C = G@P (32..39), Y0 (40..47), Z0 (48..55)
        if (b < 32) {
            int e = b * 512 + t, i = e >> 7, j = e & 127;
            const float* a0 = &g_A0[i * 128];
            float s = 0.f;
#pragma unroll 8
            for (int k = 0; k < 128; k++) s += __ldcg(a0 + k) * P[k * 128 + j];
            g_A[e] = s;
        } else if (b < 40) {
            int e = (b - 32) * 512 + t, i = e >> 7, j = e & 127;
            float s = 0.f;
#pragma unroll 8
            for (int k = 0; k < 128; k++) s += G[i * 128 + k] * P[k * 128 + j];
            g_C[e] = s;
        } else if (b < 48) {
            float ic = __ldcg(&g_scal[0]);
            int base = (b - 40) * 2048 + t;
#pragma unroll
            for (int r = 0; r < 4; r++) g_Ybuf[0][base + r * 512] = Q[base + r * 512] * ic;
        } else if (b < 56) {
            int base = (b - 48) * 2048 + t;
#pragma unroll
            for (int r = 0; r < 4; r++) { int e = base + r * 512; g_Zbuf[0][e] = ((e >> 7) == (e & 127)) ? 1.f : 0.f; }
        }
        sbar(&g_c1, &g_s1, SET_CTAS, 0u);

        // phase 2: NS (CTAs 0..63) || warp-Lanczos (CTA 64)
        if (b < NSC) {
            unsigned s2 = 0;
            int p = 0;
            int half = t >> 8, tt = t & 255;
            int i = tt >> 7, j = tt & 127;
            int r0 = b * 2;
            for (int it = 0; it < NS_ITERS; it++) {
                const float* Y = g_Ybuf[p];
                const float* Z = g_Zbuf[p];
                float* Yn = g_Ybuf[p ^ 1];
                float* Zn = g_Zbuf[p ^ 1];
                if (half == 0) {
                    for (int q = tt; q < 4096; q += 256) ((float4*)sA)[q] = __ldcg(((const float4*)Y) + q);
                    rowb[i][j] = __ldcg(&Z[(r0 + i) * 128 + j]);
                } else {
                    for (int q = tt; q < 4096; q += 256) ((float4*)sZ)[q] = __ldcg(((const float4*)Z) + q);
                }
                __syncthreads();
                if (half == 0) {
                    const float* rw = rowb[i];
                    float s = 0.f;
#pragma unroll 8
                    for (int k = 0; k < 128; k++) s += rw[k] * sA[k * 128 + j];
                    g_T[(r0 + i) * 128 + j] = (((r0 + i) == j) ? 1.5f : 0.f) - 0.5f * s;
                }
                s2 ^= 1; sbar(&g_c2, &g_s2, NSC, s2);
                for (int q = t; q < 4096; q += 512)
                    ((float4*)sA)[q] = __ldcg(((const float4*)g_T) + q);
                if (half == 0) rowb[i][j] = __ldcg(&Y[(r0 + i) * 128 + j]);
                __syncthreads();
                if (half == 0) {
                    const float* rw = rowb[i];
                    float s = 0.f;
#pragma unroll 8
                    for (int k = 0; k < 128; k++) s += rw[k] * sA[k * 128 + j];
                    Yn[(r0 + i) * 128 + j] = s;
                } else {
                    const float* tr = &sA[(r0 + i) * 128];
                    float s = 0.f;
#pragma unroll 8
                    for (int k = 0; k < 128; k++) s += tr[k] * sZ[k * 128 + j];
                    Zn[(r0 + i) * 128 + j] = s;
                }
                s2 ^= 1; sbar(&g_c2, &g_s2, NSC, s2);
                __syncthreads();
                p ^= 1;
            }
        } else {
            // Lanczos lam_max(HtH), one warp, shfl reductions
            float* sM = sA;
            for (int q = t; q < 4096; q += 512) sM[q] = __ldcg(&g_HtH[q]);
            __syncthreads();
            if (t < 32) {
                int l2 = t * 2;
                float r0 = 0.f, r1 = 0.f;
#pragma unroll 8
                for (int k = 0; k < 64; k++) { r0 += sM[l2 * 64 + k]; r1 += sM[(l2 + 1) * 64 + k]; }
                float nn = r0 * r0 + r1 * r1;
#pragma unroll
                for (int o = 16; o > 0; o >>= 1) nn += __shfl_xor_sync(0xFFFFFFFFu, nn, o);
                float inv = rsqrtf(nn);
                sv[l2] = r0 * inv; sv[l2 + 1] = r1 * inv;
                svp[l2] = 0.f; svp[l2 + 1] = 0.f;
                if (t == 0) s_be[0] = 0.f;
                float bprev = 0.f;
                for (int jj = 0; jj < LAN_M; jj++) {
                    __syncwarp();
                    float w0 = 0.f, w1 = 0.f;
#pragma unroll 8
                    for (int k = 0; k < 64; k++) {
                        float vk = sv[k];
                        w0 += sM[l2 * 64 + k] * vk;
                        w1 += sM[(l2 + 1) * 64 + k] * vk;
                    }
                    w0 -= bprev * svp[l2];
                    w1 -= bprev * svp[l2 + 1];
                    float ap = w0 * sv[l2] + w1 * sv[l2 + 1];
#pragma unroll
                    for (int o = 16; o > 0; o >>= 1) ap += __shfl_xor_sync(0xFFFFFFFFu, ap, o);
                    w0 -= ap * sv[l2]; w1 -= ap * sv[l2 + 1];
                    float b2 = w0 * w0 + w1 * w1;
#pragma unroll
                    for (int o = 16; o > 0; o >>= 1) b2 += __shfl_xor_sync(0xFFFFFFFFu, b2, o);
                    float bn = sqrtf(b2);
                    if (t == 0) { s_al[jj] = ap; s_be[jj + 1] = bn; }
                    svp[l2] = sv[l2]; svp[l2 + 1] = sv[l2 + 1];
                    float ib = (bn > 1e-12f) ? (1.f / bn) : 0.f;
                    __syncwarp();
                    sv[l2] = w0 * ib; sv[l2 + 1] = w1 * ib;
                    bprev = bn;
                }
            }
            __syncthreads();
            if (t == 0) {
                float hi = 0.f;
                for (int jj = 0; jj < LAN_M; jj++) {
                    float g = s_al[jj] + fabsf(s_be[jj]) + fabsf(s_be[jj + 1]);
                    if (g > hi) hi = g;
                }
                l_lo = 0.f; l_hi = hi + 1.f;
            }
            __syncthreads();
            for (int r = 0; r < 5; r++) {
                float lo = l_lo, hi = l_hi;
                if (t < 64) {
                    float xm = lo + (hi - lo) * (float)(t + 1) * (1.f / 65.f);
                    int cnt = 0; float d = 1.f;
                    for (int jj = 0; jj < LAN_M; jj++) {
                        float bj = (jj == 0) ? 0.f : s_be[jj];
                        d = (s_al[jj] - xm) - __fdividef(bj * bj, d);
                        if (d == 0.f) d = -1e-30f;
                        if (d < 0.f) cnt++;
                    }
                    l_flag[t] = (cnt >= LAN_M) ? 1 : 0;
                }
                __syncthreads();
                if (t == 0) {
                    float nlo = lo, nhi = hi;
                    for (int q = 0; q < 64; q++) {
                        float sq = lo + (hi - lo) * (float)(q + 1) * (1.f / 65.f);
                        if (l_flag[q]) { nhi = sq; break; }
                        nlo = sq;
                    }
                    l_lo = nlo; l_hi = nhi;
                }
                __syncthreads();
            }
            if (t == 0) {
                float lam = 0.5f * (l_lo + l_hi);
                if (lam < 1e-20f) lam = 1e-20f;
                float cfro = __ldcg(&g_scal[2]);
                g_scal[1] = sqrtf(cfro) / (1.01f * sqrtf(lam));
            }
        }
        sbar(&g_c1, &g_s1, SET_CTAS, 1u);

        // phase 3: packW (B inline)
        {
            int idx = b * 512 + t;
            if (idx < 30720) {
                int o = idx / 192, k = idx % 192;
                float v;
                if (k < 128) {
                    v = (o < 128) ? __ldcg(&g_A[o * 128 + k]) : __ldcg(&g_C[(o - 128) * 128 + k]);
                } else if (o < 128) {
                    const float* yr = &g_Ybuf[0][o * 128];
                    int j = k - 128;
                    float s0 = 0.f, s1 = 0.f;
#pragma unroll 4
                    for (int kk = 0; kk < 128; kk += 2) {
                        s0 += __ldcg(yr + kk) * H[kk * 64 + j];
                        s1 += __ldcg(yr + kk + 1) * H[(kk + 1) * 64 + j];
                    }
                    v = (s0 + s1) * __ldcg(&g_scal[1]);
                } else {
                    v = 0.f;
                }
                __nv_bfloat16 h = __float2bfloat16_rn(v);
                __nv_bfloat16 l = __float2bfloat16_rn(v - __bfloat162float(h));
                uint32_t boff = (uint32_t)(((o >> 3) + (k >> 6) * 20) * 1024 + (o & 7) * 128 + (k & 63) * 2);
                uint32_t sw = boff ^ ((boff >> 3) & 0x70);
                *(unsigned short*)(g_Wimg + sw) = __bfloat16_as_ushort(h);
                *(unsigned short*)(g_Wimg + W_IMG_HALF + sw) = __bfloat16_as_ushort(l);
            }
        }
        sbar(&g_c1, &g_s1, SET_CTAS, 0u);
    }

    // ===== global join: all 152 CTAs =====
    sbar(&g_c3, &g_s3, GRID, 1u);

#if TC_OK
    // ===== GEMM persistent loop =====
    {
        int wid = t >> 5;
        int sub = wid & 3;
        int grp = wid >> 2;
        int lane = t & 31;
        uint32_t smbase = smem_u32(smraw);
        uint32_t wbase = (smbase + 1023u) & ~1023u;
        unsigned char* wptr = smraw + (wbase - smbase);
        unsigned char* aslots = wptr + W_IMG_BYTES;
        {
            const float4* src = (const float4*)g_Wimg;
            float4* dst = (float4*)wptr;
            for (int i = t; i < W_IMG_BYTES / 16; i += 512) dst[i] = src[i];
        }
        __syncthreads();
        uint32_t tb = s_tptr;
        uint32_t mb = smem_u32(&s_mbar);
        uint64_t descH = make_desc(wbase);
        uint64_t descL = make_desc(wbase + W_IMG_HALF);
        uint32_t wofs = (uint32_t)sub << 21;
        uint32_t parity = 0;
        int prev = -1;
        int buf = 0, prevbuf = 0;

        uint32_t slotWarp[3];
        uint32_t tcol[3];
        int jarr[3];
#pragma unroll
        for (int k = 0; k < 3; k++) {
            int j = grp + 4 * k;
            jarr[k] = j;
            int c = j >> 1, half = j & 1;
            slotWarp[k] = smem_u32(aslots + (wid * 3 + k) * 2048);
            tcol[k] = (uint32_t)(half * 96 + c * 16);
        }
        // plane layout [q][row][16B]: this warp needs rows sub*32..sub*32+31
        uint32_t srcOff = (uint32_t)((sub * 32 + lane) * 16);   // + q*2048
        uint32_t dstOff = (uint32_t)(lane * 16);                // + q*512

        if (b < ntiles) {
#pragma unroll
            for (int k = 0; k < 3; k++) {
                const char* gb = (const char*)g_xbf + (((size_t)b * 12 + jarr[k]) * 8192);
#pragma unroll
                for (int q = 0; q < 4; q++)
                    CP_ASYNC16(slotWarp[k] + q * 512 + dstOff, gb + q * 2048 + srcOff);
            }
        }
        CP_COMMIT();

        for (int tile = b; tile < ntiles; tile += GRID) {
            if (prev >= 0) { MBARRIER_WAIT_PARITY(mb, parity); parity ^= 1; TCGEN05_FENCE_AFTER(); }
            CP_WAIT0();
            __syncwarp();
#pragma unroll
            for (int k = 0; k < 3; k++) {
                const unsigned char* sp = aslots + (wid * 3 + k) * 2048;
                uint4 a0 = *(const uint4*)(sp + 0 * 512 + lane * 16);
                uint4 a1 = *(const uint4*)(sp + 1 * 512 + lane * 16);
                uint4 a2 = *(const uint4*)(sp + 2 * 512 + lane * 16);
                uint4 a3 = *(const uint4*)(sp + 3 * 512 + lane * 16);
                uint32_t pk[16] = {a0.x, a0.y, a0.z, a0.w, a1.x, a1.y, a1.z, a1.w,
                                   a2.x, a2.y, a2.z, a2.w, a3.x, a3.y, a3.z, a3.w};
                TCGEN05_ST_X16(tb + tcol[k] + wofs, pk);
            }
            TCGEN05_WAIT_ST();
            TCGEN05_FENCE_BEFORE();
            __syncthreads();
            uint32_t dcol = tb + 192u + (uint32_t)buf * 160u;
            if (t < 32) {
                TCGEN05_FENCE_AFTER();
                if (elect_one_pred()) {
                    int idx = 0;
#pragma unroll
                    for (int term = 0; term < 3; term++) {
                        uint32_t ab = tb + ((term == 2) ? 96u : 0u);
                        uint64_t bd = (term == 1) ? descL : descH;
#pragma unroll
                        for (int k = 0; k < 12; k++) {
                            uint64_t d = bd + (uint64_t)((k >> 2) * 1280 + (k & 3) * 2);
                            TCGEN05_MMA_F16(dcol, ab + (uint32_t)(k * 8), d, IDESC_MAIN, idx > 0);
                            idx++;
                        }
                    }
                    TCGEN05_COMMIT(mb);
                }
            }
            int nxt = tile + GRID;
            if (nxt < ntiles) {
#pragma unroll
                for (int k = 0; k < 3; k++) {
                    const char* gb = (const char*)g_xbf + (((size_t)nxt * 12 + jarr[k]) * 8192);
#pragma unroll
                    for (int q = 0; q < 4; q++)
                        CP_ASYNC16(slotWarp[k] + q * 512 + dstOff, gb + q * 2048 + srcOff);
                }
            }
            CP_COMMIT();
            if (prev >= 0)
                epi512(tb + 192u + (uint32_t)prevbuf * 160u, prev, sub, lane, grp, dx, y);
            prev = tile;
            prevbuf = buf;
            buf ^= 1;
        }
        if (prev >= 0) {
            MBARRIER_WAIT_PARITY(mb, parity); parity ^= 1;
            TCGEN05_FENCE_AFTER();
            epi512(tb + 192u + (uint32_t)prevbuf * 160u, prev, sub, lane, grp, dx, y);
        }
        __syncthreads();
        if (t < 32) TCGEN05_DEALLOC(tb, 512);
    }
#else
    // Generic-PTX fallback (never executed on GB300).
    for (int tile = b; tile < ntiles; tile += GRID) {
        for (int rr = t; rr < 128; rr += 512) {
            size_t s = (size_t)tile * 128 + rr;
            const float* xr = &x[s * 128];
            for (int o = 0; o < 128; o++) {
                float acc = 0.f;
                for (int k = 0; k < 128; k++) acc += xr[k] * g_A[o * 128 + k];
                dx[s * 128 + o] = acc;
            }
            for (int o = 0; o < 32; o++) {
                float acc = 0.f;
                for (int k = 0; k < 128; k++) acc += xr[k] * g_C[o * 128 + k];
                y[s * 32 + o] = acc;
            }
        }
    }
#endif

    // final join: returns g_s3 to 0 for replay-safety
    sbar(&g_c3, &g_s3, GRID, 0u);
}

// ---------------- launcher (single launch) ----------------
extern "C" void kernel_launch(void* const* d_in, const int* in_sizes, int n_in,
                              void* d_out, int out_size) {
    const float* u = (const float*)d_in[0];
    const float* x = (const float*)d_in[1];
    const float* Q = (const float*)d_in[2];
    const float* P = (const float*)d_in[3];
    const float* S = (const float*)d_in[4];
    const float* G = (const float*)d_in[5];
    const float* H = (const float*)d_in[6];
    int N = in_sizes[0] / 64;
    float* dx = (float*)d_out;
    float* y = dx + (size_t)N * 128;
    int ntiles = N / 128;
    if (ntiles > MAX_TILES) ntiles = MAX_TILES;

    int smem = 1024 + W_IMG_BYTES + 48 * 2048;
    cudaFuncSetAttribute(k_fused, cudaFuncAttributeMaxDynamicSharedMemorySize, smem);
    k_fused<<<GRID, 512, smem>>>(Q, P, S, G, H, x, u, dx, y, ntiles);
}